// round 12
// baseline (speedup 1.0000x reference)
#include <cuda_runtime.h>
#include <cuda_fp16.h>
#include <cuda_bf16.h>
#include <cstdint>

#define B_   16384
#define T_   4
#define D_   1024
#define MROWS (B_*T_)
#define N1   (3*D_)

__device__ __half g_X [(size_t)MROWS*D_];
__device__ __half g_W1[(size_t)D_*N1];
__device__ __half g_W2[(size_t)D_*D_];
__device__ __half g_qkv[(size_t)MROWS*N1];
__device__ float  g_uq[(size_t)MROWS*8];
__device__ float  g_uv[(size_t)MROWS*8];
__device__ __half g_M [(size_t)B_*D_];
__device__ float  g_P [(size_t)B_*8];
__device__ uint4  g_Aq2[1024];
__device__ uint4  g_Av2[1024];

// ---------------- fp32 -> fp16 convert ----------------
__global__ void k_convert(const float* __restrict__ src, __half* __restrict__ dst, int n4) {
    int i = blockIdx.x * blockDim.x + threadIdx.x;
    if (i >= n4) return;
    float4 v = ((const float4*)src)[i];
    ((__half2*)dst)[2*i]   = __halves2half2(__float2half_rn(v.x), __float2half_rn(v.y));
    ((__half2*)dst)[2*i+1] = __halves2half2(__float2half_rn(v.z), __float2half_rn(v.w));
}

// ---------------- LoRA-A -> packed bf16 ----------------
__global__ void k_convA(const float* __restrict__ Aq, const float* __restrict__ Av) {
    int d = blockIdx.x * 256 + threadIdx.x;
    if (d >= 1024) return;
    uint4 oq, ov;
    __nv_bfloat162* pq = (__nv_bfloat162*)&oq;
    __nv_bfloat162* pv = (__nv_bfloat162*)&ov;
    #pragma unroll
    for (int r = 0; r < 4; r++) {
        pq[r] = __nv_bfloat162(__float2bfloat16_rn(Aq[d*8 + 2*r]), __float2bfloat16_rn(Aq[d*8 + 2*r + 1]));
        pv[r] = __nv_bfloat162(__float2bfloat16_rn(Av[d*8 + 2*r]), __float2bfloat16_rn(Av[d*8 + 2*r + 1]));
    }
    g_Aq2[d] = oq;
    g_Av2[d] = ov;
}

// ---------------- fused: x+tp -> fp16 AND u = (x+tp)@A ----------------
__global__ void __launch_bounds__(256) k_prep(const float4* __restrict__ x4,
                                              const float4* __restrict__ tp4) {
    __shared__ uint4 sAq[1024];   // layout [c][d4]
    __shared__ uint4 sAv[1024];
    int tid = threadIdx.x;
    for (int i = tid; i < 1024; i += 256) {
        int p = (i & 3) * 256 + (i >> 2);
        sAq[p] = g_Aq2[i];
        sAv[p] = g_Av2[i];
    }
    __syncthreads();
    int w = tid >> 5, lane = tid & 31;
    int row = (blockIdx.x << 3) + w;
    int t = row & 3;
    const float4* xr = x4 + (size_t)row * 256;
    const float4* tr = tp4 + t * 256;
    __half2* Hx = (__half2*)(g_X + (size_t)row * 1024);
    float pq[8] = {0,0,0,0,0,0,0,0};
    float pv[8] = {0,0,0,0,0,0,0,0};
    #pragma unroll
    for (int j = 0; j < 8; j++) {
        int d4 = j*32 + lane;
        float4 v = xr[d4], p = tr[d4];
        v.x += p.x; v.y += p.y; v.z += p.z; v.w += p.w;
        Hx[2*d4]   = __halves2half2(__float2half_rn(v.x), __float2half_rn(v.y));
        Hx[2*d4+1] = __halves2half2(__float2half_rn(v.z), __float2half_rn(v.w));
        const float* ve = &v.x;
        #pragma unroll
        for (int c = 0; c < 4; c++) {
            float xe = ve[c];
            uint4 aq = sAq[c*256 + d4];
            uint4 av = sAv[c*256 + d4];
            const __nv_bfloat162* q2 = (const __nv_bfloat162*)&aq;
            const __nv_bfloat162* v2 = (const __nv_bfloat162*)&av;
            #pragma unroll
            for (int r = 0; r < 4; r++) {
                float2 fq = __bfloat1622float2(q2[r]);
                float2 fv = __bfloat1622float2(v2[r]);
                pq[2*r]   += xe * fq.x;
                pq[2*r+1] += xe * fq.y;
                pv[2*r]   += xe * fv.x;
                pv[2*r+1] += xe * fv.y;
            }
        }
    }
    #pragma unroll
    for (int off = 16; off > 0; off >>= 1)
        #pragma unroll
        for (int r = 0; r < 8; r++) {
            pq[r] += __shfl_xor_sync(0xffffffffu, pq[r], off);
            pv[r] += __shfl_xor_sync(0xffffffffu, pv[r], off);
        }
    if (lane == 0) {
        ((float4*)(g_uq + (size_t)row*8))[0] = make_float4(pq[0],pq[1],pq[2],pq[3]);
        ((float4*)(g_uq + (size_t)row*8))[1] = make_float4(pq[4],pq[5],pq[6],pq[7]);
        ((float4*)(g_uv + (size_t)row*8))[0] = make_float4(pv[0],pv[1],pv[2],pv[3]);
        ((float4*)(g_uv + (size_t)row*8))[1] = make_float4(pv[4],pv[5],pv[6],pv[7]);
    }
}

// ---------------- single-fp16 GEMM, CTA 128x128, warp 32x64, K-chunk 128, 2-stage ----------------
#define ASTAGE 34816              // 128 rows x 272B (128 cols + 8 pad)
#define BSTAGE 34816              // 128 rows x 272B (128 cols + 8 pad)
#define STAGE  (ASTAGE + BSTAGE)  // 69632
#define SMEM_BYTES (2*STAGE)      // 139264
__device__ __forceinline__ uint32_t sA(int buf, int row, int col) {
    return (uint32_t)(buf*STAGE + row*272 + col*2);
}
__device__ __forceinline__ uint32_t sB(int buf, int row, int col) {
    return (uint32_t)(buf*STAGE + ASTAGE + row*272 + col*2);
}
#define CP16(dst, src) asm volatile("cp.async.cg.shared.global [%0], [%1], 16;\n" :: "r"(dst), "l"(src))
#define LDSM4(R, addr) asm volatile("ldmatrix.sync.aligned.m8n8.x4.shared.b16 {%0,%1,%2,%3}, [%4];\n" \
    : "=r"((R)[0]), "=r"((R)[1]), "=r"((R)[2]), "=r"((R)[3]) : "r"(addr))
#define LDSM4T(R, addr) asm volatile("ldmatrix.sync.aligned.m8n8.x4.trans.shared.b16 {%0,%1,%2,%3}, [%4];\n" \
    : "=r"((R)[0]), "=r"((R)[1]), "=r"((R)[2]), "=r"((R)[3]) : "r"(addr))
#define MMAF32(Dp, A, Bf) asm volatile( \
    "mma.sync.aligned.m16n8k16.row.col.f32.f16.f16.f32 {%0,%1,%2,%3},{%4,%5,%6,%7},{%8,%9},{%0,%1,%2,%3};\n" \
    : "+f"((Dp)[0]), "+f"((Dp)[1]), "+f"((Dp)[2]), "+f"((Dp)[3]) \
    : "r"((A)[0]), "r"((A)[1]), "r"((A)[2]), "r"((A)[3]), "r"((Bf)[0]), "r"((Bf)[1]))

__device__ __forceinline__ void store2(__half* p, float v0, float v1) {
    *(__half2*)p = __floats2half2_rn(v0, v1);
}
__device__ __forceinline__ void store2(float* p, float v0, float v1) {
    float2 o; o.x = v0; o.y = v1;
    *(float2*)p = o;
}

template<bool EPI, typename OT>
__global__ void __launch_bounds__(256) k_gemm(
    const __half* __restrict__ Ag, const __half* __restrict__ Bg,
    OT* __restrict__ C, int N, int K,
    const float* __restrict__ bias, const float* __restrict__ P,
    const float* __restrict__ LB)
{
    extern __shared__ __align__(16) char smem[];
    uint32_t sb = (uint32_t)__cvta_generic_to_shared(smem);
    int tid = threadIdx.x;
    int bm = blockIdx.y << 7, bn = blockIdx.x << 7;
    int KT = K >> 7;

    float d[2][8][4];
    #pragma unroll
    for (int i = 0; i < 2; i++)
        #pragma unroll
        for (int j = 0; j < 8; j++) { d[i][j][0]=0.f; d[i][j][1]=0.f; d[i][j][2]=0.f; d[i][j][3]=0.f; }

    int w = tid >> 5, lane = tid & 31;
    int wm = w & 3, wn = w >> 2;
    int r0 = tid >> 4, c0 = (tid & 15) << 3;   // 16 chunks per 128-col row

    auto load_stage = [&](int kt, int buf) {
        #pragma unroll
        for (int i = 0; i < 8; i++) {
            int arow = r0 + i*16;
            CP16(sb + sA(buf, arow, c0), Ag + (size_t)(bm + arow) * K + (kt<<7) + c0);
        }
        #pragma unroll
        for (int i = 0; i < 8; i++) {
            int brow = r0 + i*16;
            CP16(sb + sB(buf, brow, c0), Bg + (size_t)((kt<<7) + brow) * N + bn + c0);
        }
        asm volatile("cp.async.commit_group;\n");
    };

    load_stage(0, 0);
    int sub = lane >> 3, rr = lane & 7;
    int bl15 = lane & 15, blh = (lane >> 4) << 3;

    auto ldA = [&](int buf, int ks, uint32_t (*a)[4]) {
        #pragma unroll
        for (int mt = 0; mt < 2; mt++) {
            int arow = (wm<<5) + (mt<<4) + ((sub&1)<<3) + rr;
            int acol = (ks<<4) + ((sub>>1)<<3);
            LDSM4(a[mt], sb + sA(buf, arow, acol));
        }
    };
    auto ldB = [&](int buf, int ks, uint32_t (*b)[2]) {
        int krow = (ks<<4) + bl15;
        #pragma unroll
        for (int p = 0; p < 4; p++) {
            uint32_t r4[4];
            int bcol = (wn<<6) + (p<<4) + blh;
            LDSM4T(r4, sb + sB(buf, krow, bcol));
            b[2*p][0] = r4[0];   b[2*p][1] = r4[1];
            b[2*p+1][0] = r4[2]; b[2*p+1][1] = r4[3];
        }
    };

    for (int kt = 0; kt < KT; kt++) {
        asm volatile("cp.async.wait_group 0;\n" ::: "memory");
        __syncthreads();
        int buf = kt & 1;
        if (kt + 1 < KT) load_stage(kt + 1, buf ^ 1);

        uint32_t a[2][2][4], b[2][8][2];
        ldA(buf, 0, a[0]);
        ldB(buf, 0, b[0]);
        #pragma unroll
        for (int ks = 0; ks < 8; ks++) {
            int cur = ks & 1, nxt = cur ^ 1;
            if (ks < 7) {
                ldA(buf, ks + 1, a[nxt]);
                ldB(buf, ks + 1, b[nxt]);
            }
            #pragma unroll
            for (int mt = 0; mt < 2; mt++)
                #pragma unroll
                for (int nt = 0; nt < 8; nt++)
                    MMAF32(d[mt][nt], a[cur][mt], b[cur][nt]);
        }
    }

    int g = lane >> 2, tq = (lane & 3) << 1;
    #pragma unroll
    for (int mt = 0; mt < 2; mt++)
        #pragma unroll
        for (int e2 = 0; e2 < 2; e2++) {
            int row = bm + (wm<<5) + (mt<<4) + (e2<<3) + g;
            float p0=0,p1=0,p2=0,p3=0,p4=0,p5=0,p6=0,p7=0;
            if (EPI) {
                const float* pr = P + (size_t)row*8;
                p0=pr[0];p1=pr[1];p2=pr[2];p3=pr[3];
                p4=pr[4];p5=pr[5];p6=pr[6];p7=pr[7];
            }
            #pragma unroll
            for (int nt = 0; nt < 8; nt++) {
                int col = bn + (wn<<6) + (nt<<3) + tq;
                float v0 = d[mt][nt][e2*2], v1 = d[mt][nt][e2*2+1];
                if (EPI) {
                    v0 += bias[col] + 2.f*(p0*LB[col] + p1*LB[N+col] + p2*LB[2*N+col] + p3*LB[3*N+col]
                        + p4*LB[4*N+col] + p5*LB[5*N+col] + p6*LB[6*N+col] + p7*LB[7*N+col]);
                    v1 += bias[col+1] + 2.f*(p0*LB[col+1] + p1*LB[N+col+1] + p2*LB[2*N+col+1] + p3*LB[3*N+col+1]
                        + p4*LB[4*N+col+1] + p5*LB[5*N+col+1] + p6*LB[6*N+col+1] + p7*LB[7*N+col+1]);
                }
                store2(C + (size_t)row*N + col, v0, v1);
            }
        }
}

// ---------------- attention + mean + M + P ----------------
__global__ void __launch_bounds__(512) k_attn(const float* __restrict__ Bq,
                                              const float* __restrict__ Bv,
                                              const float* __restrict__ Apj) {
    __shared__ float pacc[8];
    int tid = threadIdx.x;
    if (tid < 8) pacc[tid] = 0.f;
    __syncthreads();
    int b = blockIdx.x;
    int h = tid >> 5, lane = tid & 31;
    int row0 = b << 2;
    int c0 = (h << 6) + lane;

    float q[4][2], k[4][2], v[4][2];
    #pragma unroll
    for (int t = 0; t < 4; t++) {
        size_t base = (size_t)(row0 + t) * 3072;
        const float* uqr = g_uq + (size_t)(row0 + t) * 8;
        const float* uvr = g_uv + (size_t)(row0 + t) * 8;
        float dq0=0, dq1=0, dv0=0, dv1=0;
        #pragma unroll
        for (int r = 0; r < 8; r++) {
            float uqv = uqr[r], uvv = uvr[r];
            dq0 += uqv * Bq[r*1024 + c0];
            dq1 += uqv * Bq[r*1024 + c0 + 32];
            dv0 += uvv * Bv[r*1024 + c0];
            dv1 += uvv * Bv[r*1024 + c0 + 32];
        }
        q[t][0] = __half2float(g_qkv[base + c0])        + 2.f*dq0;
        q[t][1] = __half2float(g_qkv[base + c0 + 32])   + 2.f*dq1;
        k[t][0] = __half2float(g_qkv[base + 1024 + c0]);
        k[t][1] = __half2float(g_qkv[base + 1024 + c0 + 32]);
        v[t][0] = __half2float(g_qkv[base + 2048 + c0])      + 2.f*dv0;
        v[t][1] = __half2float(g_qkv[base + 2048 + c0 + 32]) + 2.f*dv1;
    }
    float sc[4][4];
    #pragma unroll
    for (int t = 0; t < 4; t++)
        #pragma unroll
        for (int s = 0; s < 4; s++) {
            float p = q[t][0]*k[s][0] + q[t][1]*k[s][1];
            #pragma unroll
            for (int off = 16; off > 0; off >>= 1)
                p += __shfl_xor_sync(0xffffffffu, p, off);
            sc[t][s] = p * 0.125f;
        }
    float a0 = 0.f, a1 = 0.f;
    #pragma unroll
    for (int t = 0; t < 4; t++) {
        float m = fmaxf(fmaxf(sc[t][0], sc[t][1]), fmaxf(sc[t][2], sc[t][3]));
        float e0 = __expf(sc[t][0]-m), e1 = __expf(sc[t][1]-m);
        float e2 = __expf(sc[t][2]-m), e3 = __expf(sc[t][3]-m);
        float inv = 1.f / (e0+e1+e2+e3);
        a0 += (e0*v[0][0] + e1*v[1][0] + e2*v[2][0] + e3*v[3][0]) * inv;
        a1 += (e0*v[0][1] + e1*v[1][1] + e2*v[2][1] + e3*v[3][1]) * inv;
    }
    a0 *= 0.25f; a1 *= 0.25f;
    size_t oi = (size_t)b*1024 + c0;
    g_M[oi]    = __float2half_rn(a0);
    g_M[oi+32] = __float2half_rn(a1);
    float pp[8];
    #pragma unroll
    for (int r = 0; r < 8; r++)
        pp[r] = a0 * Apj[(size_t)c0*8 + r] + a1 * Apj[(size_t)(c0+32)*8 + r];
    #pragma unroll
    for (int off = 16; off > 0; off >>= 1)
        #pragma unroll
        for (int r = 0; r < 8; r++)
            pp[r] += __shfl_xor_sync(0xffffffffu, pp[r], off);
    if (lane == 0) {
        #pragma unroll
        for (int r = 0; r < 8; r++) atomicAdd(&pacc[r], pp[r]);
    }
    __syncthreads();
    if (tid < 8) g_P[(size_t)b*8 + tid] = pacc[tid];
}

extern "C" void kernel_launch(void* const* d_in, const int* in_sizes, int n_in,
                              void* d_out, int out_size) {
    const float* x    = (const float*)d_in[0];
    const float* tp   = (const float*)d_in[1];
    const float* Wqkv = (const float*)d_in[2];
    const float* lqA  = (const float*)d_in[3];
    const float* lqB  = (const float*)d_in[4];
    const float* lvA  = (const float*)d_in[5];
    const float* lvB  = (const float*)d_in[6];
    const float* Wp   = (const float*)d_in[7];
    const float* bp   = (const float*)d_in[8];
    const float* lpA  = (const float*)d_in[9];
    const float* lpB  = (const float*)d_in[10];
    float* out = (float*)d_out;

    static bool attr_set = false;
    if (!attr_set) {
        cudaFuncSetAttribute(k_gemm<false, __half>, cudaFuncAttributeMaxDynamicSharedMemorySize, SMEM_BYTES);
        cudaFuncSetAttribute(k_gemm<true, float>,   cudaFuncAttributeMaxDynamicSharedMemorySize, SMEM_BYTES);
        attr_set = true;
    }

    void *pX, *pW1, *pW2, *pQkv, *pM, *pP;
    cudaGetSymbolAddress(&pX,  g_X);
    cudaGetSymbolAddress(&pW1, g_W1);
    cudaGetSymbolAddress(&pW2, g_W2);
    cudaGetSymbolAddress(&pQkv, g_qkv);
    cudaGetSymbolAddress(&pM,  g_M);
    cudaGetSymbolAddress(&pP,  g_P);

    k_convert<<<3072, 256>>>(Wqkv, (__half*)pW1, 786432);
    k_convert<<<1024, 256>>>(Wp,   (__half*)pW2, 262144);
    k_convA<<<4, 256>>>(lqA, lvA);
    k_prep<<<8192, 256>>>((const float4*)x, (const float4*)tp);

    k_gemm<false, __half><<<dim3(24, 512), 256, SMEM_BYTES>>>(
        (const __half*)pX, (const __half*)pW1,
        (__half*)pQkv, N1, D_, nullptr, nullptr, nullptr);

    k_attn<<<B_, 512>>>(lqB, lvB, lpA);

    k_gemm<true, float><<<dim3(8, 128), 256, SMEM_BYTES>>>(
        (const __half*)pM, (const __half*)pW2,
        out, D_, D_, bp, (const float*)pP, lpB);
}

// round 13
// speedup vs baseline: 1.0848x; 1.0848x over previous
#include <cuda_runtime.h>
#include <cuda_fp16.h>
#include <cuda_bf16.h>
#include <cstdint>

#define B_   16384
#define T_   4
#define D_   1024
#define MROWS (B_*T_)
#define N1   (3*D_)

__device__ __half g_X [(size_t)MROWS*D_];
__device__ __half g_W1[(size_t)D_*N1];
__device__ __half g_W2[(size_t)D_*D_];
__device__ __half g_qkv[(size_t)MROWS*N1];
__device__ float  g_uq[(size_t)MROWS*8];
__device__ float  g_uv[(size_t)MROWS*8];
__device__ __half g_M [(size_t)B_*D_];
__device__ float  g_P [(size_t)B_*8];
__device__ uint4  g_Aq2[1024];
__device__ uint4  g_Av2[1024];

// ---------------- fp32 -> fp16 convert ----------------
__global__ void k_convert(const float* __restrict__ src, __half* __restrict__ dst, int n4) {
    int i = blockIdx.x * blockDim.x + threadIdx.x;
    if (i >= n4) return;
    float4 v = ((const float4*)src)[i];
    ((__half2*)dst)[2*i]   = __halves2half2(__float2half_rn(v.x), __float2half_rn(v.y));
    ((__half2*)dst)[2*i+1] = __halves2half2(__float2half_rn(v.z), __float2half_rn(v.w));
}

// ---------------- LoRA-A -> packed bf16 ----------------
__global__ void k_convA(const float* __restrict__ Aq, const float* __restrict__ Av) {
    int d = blockIdx.x * 256 + threadIdx.x;
    if (d >= 1024) return;
    uint4 oq, ov;
    __nv_bfloat162* pq = (__nv_bfloat162*)&oq;
    __nv_bfloat162* pv = (__nv_bfloat162*)&ov;
    #pragma unroll
    for (int r = 0; r < 4; r++) {
        pq[r] = __nv_bfloat162(__float2bfloat16_rn(Aq[d*8 + 2*r]), __float2bfloat16_rn(Aq[d*8 + 2*r + 1]));
        pv[r] = __nv_bfloat162(__float2bfloat16_rn(Av[d*8 + 2*r]), __float2bfloat16_rn(Av[d*8 + 2*r + 1]));
    }
    g_Aq2[d] = oq;
    g_Av2[d] = ov;
}

// ---------------- fused: x+tp -> fp16 AND u = (x+tp)@A ----------------
__global__ void __launch_bounds__(256) k_prep(const float4* __restrict__ x4,
                                              const float4* __restrict__ tp4) {
    __shared__ uint4 sAq[1024];   // layout [c][d4]
    __shared__ uint4 sAv[1024];
    int tid = threadIdx.x;
    for (int i = tid; i < 1024; i += 256) {
        int p = (i & 3) * 256 + (i >> 2);
        sAq[p] = g_Aq2[i];
        sAv[p] = g_Av2[i];
    }
    __syncthreads();
    int w = tid >> 5, lane = tid & 31;
    int row = (blockIdx.x << 3) + w;
    int t = row & 3;
    const float4* xr = x4 + (size_t)row * 256;
    const float4* tr = tp4 + t * 256;
    __half2* Hx = (__half2*)(g_X + (size_t)row * 1024);
    float pq[8] = {0,0,0,0,0,0,0,0};
    float pv[8] = {0,0,0,0,0,0,0,0};
    #pragma unroll
    for (int j = 0; j < 8; j++) {
        int d4 = j*32 + lane;
        float4 v = xr[d4], p = tr[d4];
        v.x += p.x; v.y += p.y; v.z += p.z; v.w += p.w;
        Hx[2*d4]   = __halves2half2(__float2half_rn(v.x), __float2half_rn(v.y));
        Hx[2*d4+1] = __halves2half2(__float2half_rn(v.z), __float2half_rn(v.w));
        const float* ve = &v.x;
        #pragma unroll
        for (int c = 0; c < 4; c++) {
            float xe = ve[c];
            uint4 aq = sAq[c*256 + d4];
            uint4 av = sAv[c*256 + d4];
            const __nv_bfloat162* q2 = (const __nv_bfloat162*)&aq;
            const __nv_bfloat162* v2 = (const __nv_bfloat162*)&av;
            #pragma unroll
            for (int r = 0; r < 4; r++) {
                float2 fq = __bfloat1622float2(q2[r]);
                float2 fv = __bfloat1622float2(v2[r]);
                pq[2*r]   += xe * fq.x;
                pq[2*r+1] += xe * fq.y;
                pv[2*r]   += xe * fv.x;
                pv[2*r+1] += xe * fv.y;
            }
        }
    }
    #pragma unroll
    for (int off = 16; off > 0; off >>= 1)
        #pragma unroll
        for (int r = 0; r < 8; r++) {
            pq[r] += __shfl_xor_sync(0xffffffffu, pq[r], off);
            pv[r] += __shfl_xor_sync(0xffffffffu, pv[r], off);
        }
    if (lane == 0) {
        ((float4*)(g_uq + (size_t)row*8))[0] = make_float4(pq[0],pq[1],pq[2],pq[3]);
        ((float4*)(g_uq + (size_t)row*8))[1] = make_float4(pq[4],pq[5],pq[6],pq[7]);
        ((float4*)(g_uv + (size_t)row*8))[0] = make_float4(pv[0],pv[1],pv[2],pv[3]);
        ((float4*)(g_uv + (size_t)row*8))[1] = make_float4(pv[4],pv[5],pv[6],pv[7]);
    }
}

// ---------------- single-fp16 GEMM, CTA 256x128, warp 64x64, K-chunk 64, 2-stage ----------------
#define ASTAGE 36864              // 256 rows x 144B (64 cols + 8 pad)
#define BSTAGE 17408              // 64 rows x 272B (128 cols + 8 pad)
#define STAGE  (ASTAGE + BSTAGE)  // 54272
#define SMEM_BYTES (2*STAGE)      // 108544
__device__ __forceinline__ uint32_t sA(int buf, int row, int col) {
    return (uint32_t)(buf*STAGE + row*144 + col*2);
}
__device__ __forceinline__ uint32_t sB(int buf, int row, int col) {
    return (uint32_t)(buf*STAGE + ASTAGE + row*272 + col*2);
}
#define CP16(dst, src) asm volatile("cp.async.cg.shared.global [%0], [%1], 16;\n" :: "r"(dst), "l"(src))
#define LDSM4(R, addr) asm volatile("ldmatrix.sync.aligned.m8n8.x4.shared.b16 {%0,%1,%2,%3}, [%4];\n" \
    : "=r"((R)[0]), "=r"((R)[1]), "=r"((R)[2]), "=r"((R)[3]) : "r"(addr))
#define LDSM4T(R, addr) asm volatile("ldmatrix.sync.aligned.m8n8.x4.trans.shared.b16 {%0,%1,%2,%3}, [%4];\n" \
    : "=r"((R)[0]), "=r"((R)[1]), "=r"((R)[2]), "=r"((R)[3]) : "r"(addr))
#define MMAF32(Dp, A, Bf) asm volatile( \
    "mma.sync.aligned.m16n8k16.row.col.f32.f16.f16.f32 {%0,%1,%2,%3},{%4,%5,%6,%7},{%8,%9},{%0,%1,%2,%3};\n" \
    : "+f"((Dp)[0]), "+f"((Dp)[1]), "+f"((Dp)[2]), "+f"((Dp)[3]) \
    : "r"((A)[0]), "r"((A)[1]), "r"((A)[2]), "r"((A)[3]), "r"((Bf)[0]), "r"((Bf)[1]))

__device__ __forceinline__ void store2(__half* p, float v0, float v1) {
    *(__half2*)p = __floats2half2_rn(v0, v1);
}
__device__ __forceinline__ void store2(float* p, float v0, float v1) {
    float2 o; o.x = v0; o.y = v1;
    *(float2*)p = o;
}

template<bool EPI, typename OT>
__global__ void __launch_bounds__(256) k_gemm(
    const __half* __restrict__ Ag, const __half* __restrict__ Bg,
    OT* __restrict__ C, int N, int K,
    const float* __restrict__ bias, const float* __restrict__ P,
    const float* __restrict__ LB)
{
    extern __shared__ __align__(16) char smem[];
    uint32_t sb = (uint32_t)__cvta_generic_to_shared(smem);
    int tid = threadIdx.x;
    int bm = blockIdx.y << 8, bn = blockIdx.x << 7;
    int KT = K >> 6;

    float d[4][8][4];
    #pragma unroll
    for (int i = 0; i < 4; i++)
        #pragma unroll
        for (int j = 0; j < 8; j++) { d[i][j][0]=0.f; d[i][j][1]=0.f; d[i][j][2]=0.f; d[i][j][3]=0.f; }

    int w = tid >> 5, lane = tid & 31;
    int wm = w & 3, wn = w >> 2;                // 4(M) x 2(N) warps, warp tile 64x64
    int ar0 = tid >> 3, akc = (tid & 7) << 3;   // A: 2048 chunks/stage, 8 per thread
    int br0 = tid >> 4, bnc = (tid & 15) << 3;  // B: 1024 chunks/stage, 4 per thread

    auto load_stage = [&](int kt, int buf) {
        #pragma unroll
        for (int i = 0; i < 8; i++) {
            int arow = ar0 + i*32;
            CP16(sb + sA(buf, arow, akc), Ag + (size_t)(bm + arow) * K + (kt<<6) + akc);
        }
        #pragma unroll
        for (int i = 0; i < 4; i++) {
            int brow = br0 + i*16;
            CP16(sb + sB(buf, brow, bnc), Bg + (size_t)((kt<<6) + brow) * N + bn + bnc);
        }
        asm volatile("cp.async.commit_group;\n");
    };

    load_stage(0, 0);
    int sub = lane >> 3, rr = lane & 7;
    int bl15 = lane & 15, blh = (lane >> 4) << 3;

    for (int kt = 0; kt < KT; kt++) {
        asm volatile("cp.async.wait_group 0;\n" ::: "memory");
        __syncthreads();
        int buf = kt & 1;
        if (kt + 1 < KT) load_stage(kt + 1, buf ^ 1);
        #pragma unroll
        for (int ks = 0; ks < 4; ks++) {
            uint32_t a[4][4];
            #pragma unroll
            for (int mt = 0; mt < 4; mt++) {
                int arow = (wm<<6) + (mt<<4) + ((sub&1)<<3) + rr;
                int acol = (ks<<4) + ((sub>>1)<<3);
                LDSM4(a[mt], sb + sA(buf, arow, acol));
            }
            uint32_t b[8][2];
            int krow = (ks<<4) + bl15;
            #pragma unroll
            for (int p = 0; p < 4; p++) {
                uint32_t r4[4];
                int bcol = (wn<<6) + (p<<4) + blh;
                LDSM4T(r4, sb + sB(buf, krow, bcol));
                b[2*p][0] = r4[0];   b[2*p][1] = r4[1];
                b[2*p+1][0] = r4[2]; b[2*p+1][1] = r4[3];
            }
            #pragma unroll
            for (int mt = 0; mt < 4; mt++)
                #pragma unroll
                for (int nt = 0; nt < 8; nt++)
                    MMAF32(d[mt][nt], a[mt], b[nt]);
        }
    }

    int g = lane >> 2, tq = (lane & 3) << 1;
    #pragma unroll
    for (int mt = 0; mt < 4; mt++)
        #pragma unroll
        for (int e2 = 0; e2 < 2; e2++) {
            int row = bm + (wm<<6) + (mt<<4) + (e2<<3) + g;
            float p0=0,p1=0,p2=0,p3=0,p4=0,p5=0,p6=0,p7=0;
            if (EPI) {
                const float* pr = P + (size_t)row*8;
                p0=pr[0];p1=pr[1];p2=pr[2];p3=pr[3];
                p4=pr[4];p5=pr[5];p6=pr[6];p7=pr[7];
            }
            #pragma unroll
            for (int nt = 0; nt < 8; nt++) {
                int col = bn + (wn<<6) + (nt<<3) + tq;
                float v0 = d[mt][nt][e2*2], v1 = d[mt][nt][e2*2+1];
                if (EPI) {
                    v0 += bias[col] + 2.f*(p0*LB[col] + p1*LB[N+col] + p2*LB[2*N+col] + p3*LB[3*N+col]
                        + p4*LB[4*N+col] + p5*LB[5*N+col] + p6*LB[6*N+col] + p7*LB[7*N+col]);
                    v1 += bias[col+1] + 2.f*(p0*LB[col+1] + p1*LB[N+col+1] + p2*LB[2*N+col+1] + p3*LB[3*N+col+1]
                        + p4*LB[4*N+col+1] + p5*LB[5*N+col+1] + p6*LB[6*N+col+1] + p7*LB[7*N+col+1]);
                }
                store2(C + (size_t)row*N + col, v0, v1);
            }
        }
}

// ---------------- attention + mean + M + P ----------------
__global__ void __launch_bounds__(512) k_attn(const float* __restrict__ Bq,
                                              const float* __restrict__ Bv,
                                              const float* __restrict__ Apj) {
    __shared__ float pacc[8];
    int tid = threadIdx.x;
    if (tid < 8) pacc[tid] = 0.f;
    __syncthreads();
    int b = blockIdx.x;
    int h = tid >> 5, lane = tid & 31;
    int row0 = b << 2;
    int c0 = (h << 6) + lane;

    float q[4][2], k[4][2], v[4][2];
    #pragma unroll
    for (int t = 0; t < 4; t++) {
        size_t base = (size_t)(row0 + t) * 3072;
        const float* uqr = g_uq + (size_t)(row0 + t) * 8;
        const float* uvr = g_uv + (size_t)(row0 + t) * 8;
        float dq0=0, dq1=0, dv0=0, dv1=0;
        #pragma unroll
        for (int r = 0; r < 8; r++) {
            float uqv = uqr[r], uvv = uvr[r];
            dq0 += uqv * Bq[r*1024 + c0];
            dq1 += uqv * Bq[r*1024 + c0 + 32];
            dv0 += uvv * Bv[r*1024 + c0];
            dv1 += uvv * Bv[r*1024 + c0 + 32];
        }
        q[t][0] = __half2float(g_qkv[base + c0])        + 2.f*dq0;
        q[t][1] = __half2float(g_qkv[base + c0 + 32])   + 2.f*dq1;
        k[t][0] = __half2float(g_qkv[base + 1024 + c0]);
        k[t][1] = __half2float(g_qkv[base + 1024 + c0 + 32]);
        v[t][0] = __half2float(g_qkv[base + 2048 + c0])      + 2.f*dv0;
        v[t][1] = __half2float(g_qkv[base + 2048 + c0 + 32]) + 2.f*dv1;
    }
    float sc[4][4];
    #pragma unroll
    for (int t = 0; t < 4; t++)
        #pragma unroll
        for (int s = 0; s < 4; s++) {
            float p = q[t][0]*k[s][0] + q[t][1]*k[s][1];
            #pragma unroll
            for (int off = 16; off > 0; off >>= 1)
                p += __shfl_xor_sync(0xffffffffu, p, off);
            sc[t][s] = p * 0.125f;
        }
    float a0 = 0.f, a1 = 0.f;
    #pragma unroll
    for (int t = 0; t < 4; t++) {
        float m = fmaxf(fmaxf(sc[t][0], sc[t][1]), fmaxf(sc[t][2], sc[t][3]));
        float e0 = __expf(sc[t][0]-m), e1 = __expf(sc[t][1]-m);
        float e2 = __expf(sc[t][2]-m), e3 = __expf(sc[t][3]-m);
        float inv = 1.f / (e0+e1+e2+e3);
        a0 += (e0*v[0][0] + e1*v[1][0] + e2*v[2][0] + e3*v[3][0]) * inv;
        a1 += (e0*v[0][1] + e1*v[1][1] + e2*v[2][1] + e3*v[3][1]) * inv;
    }
    a0 *= 0.25f; a1 *= 0.25f;
    size_t oi = (size_t)b*1024 + c0;
    g_M[oi]    = __float2half_rn(a0);
    g_M[oi+32] = __float2half_rn(a1);
    float pp[8];
    #pragma unroll
    for (int r = 0; r < 8; r++)
        pp[r] = a0 * Apj[(size_t)c0*8 + r] + a1 * Apj[(size_t)(c0+32)*8 + r];
    #pragma unroll
    for (int off = 16; off > 0; off >>= 1)
        #pragma unroll
        for (int r = 0; r < 8; r++)
            pp[r] += __shfl_xor_sync(0xffffffffu, pp[r], off);
    if (lane == 0) {
        #pragma unroll
        for (int r = 0; r < 8; r++) atomicAdd(&pacc[r], pp[r]);
    }
    __syncthreads();
    if (tid < 8) g_P[(size_t)b*8 + tid] = pacc[tid];
}

extern "C" void kernel_launch(void* const* d_in, const int* in_sizes, int n_in,
                              void* d_out, int out_size) {
    const float* x    = (const float*)d_in[0];
    const float* tp   = (const float*)d_in[1];
    const float* Wqkv = (const float*)d_in[2];
    const float* lqA  = (const float*)d_in[3];
    const float* lqB  = (const float*)d_in[4];
    const float* lvA  = (const float*)d_in[5];
    const float* lvB  = (const float*)d_in[6];
    const float* Wp   = (const float*)d_in[7];
    const float* bp   = (const float*)d_in[8];
    const float* lpA  = (const float*)d_in[9];
    const float* lpB  = (const float*)d_in[10];
    float* out = (float*)d_out;

    static bool attr_set = false;
    if (!attr_set) {
        cudaFuncSetAttribute(k_gemm<false, __half>, cudaFuncAttributeMaxDynamicSharedMemorySize, SMEM_BYTES);
        cudaFuncSetAttribute(k_gemm<true, float>,   cudaFuncAttributeMaxDynamicSharedMemorySize, SMEM_BYTES);
        attr_set = true;
    }

    void *pX, *pW1, *pW2, *pQkv, *pM, *pP;
    cudaGetSymbolAddress(&pX,  g_X);
    cudaGetSymbolAddress(&pW1, g_W1);
    cudaGetSymbolAddress(&pW2, g_W2);
    cudaGetSymbolAddress(&pQkv, g_qkv);
    cudaGetSymbolAddress(&pM,  g_M);
    cudaGetSymbolAddress(&pP,  g_P);

    k_convert<<<3072, 256>>>(Wqkv, (__half*)pW1, 786432);
    k_convert<<<1024, 256>>>(Wp,   (__half*)pW2, 262144);
    k_convA<<<4, 256>>>(lqA, lvA);
    k_prep<<<8192, 256>>>((const float4*)x, (const float4*)tp);

    k_gemm<false, __half><<<dim3(24, 256), 256, SMEM_BYTES>>>(
        (const __half*)pX, (const __half*)pW1,
        (__half*)pQkv, N1, D_, nullptr, nullptr, nullptr);

    k_attn<<<B_, 512>>>(lqB, lvB, lpA);

    k_gemm<true, float><<<dim3(8, 64), 256, SMEM_BYTES>>>(
        (const __half*)pM, (const __half*)pW2,
        out, D_, D_, bp, (const float*)pP, lpB);
}

// round 14
// speedup vs baseline: 1.1589x; 1.0682x over previous
#include <cuda_runtime.h>
#include <cuda_fp16.h>
#include <cuda_bf16.h>
#include <cstdint>

#define B_   16384
#define T_   4
#define D_   1024
#define MROWS (B_*T_)
#define N1   (3*D_)

__device__ __half g_X [(size_t)MROWS*D_];
__device__ __half g_W1[(size_t)D_*N1];
__device__ __half g_W2[(size_t)D_*D_];
__device__ __half g_qkv[(size_t)MROWS*N1];
__device__ float  g_uq[(size_t)MROWS*8];
__device__ float  g_uv[(size_t)MROWS*8];
__device__ __half g_M [(size_t)B_*D_];
__device__ float  g_P [(size_t)B_*8];
__device__ uint4  g_Aq2[1024];
__device__ uint4  g_Av2[1024];

// ---------------- fp32 -> fp16 convert ----------------
__global__ void k_convert(const float* __restrict__ src, __half* __restrict__ dst, int n4) {
    int i = blockIdx.x * blockDim.x + threadIdx.x;
    if (i >= n4) return;
    float4 v = ((const float4*)src)[i];
    ((__half2*)dst)[2*i]   = __halves2half2(__float2half_rn(v.x), __float2half_rn(v.y));
    ((__half2*)dst)[2*i+1] = __halves2half2(__float2half_rn(v.z), __float2half_rn(v.w));
}

// ---------------- LoRA-A -> packed bf16 ----------------
__global__ void k_convA(const float* __restrict__ Aq, const float* __restrict__ Av) {
    int d = blockIdx.x * 256 + threadIdx.x;
    if (d >= 1024) return;
    uint4 oq, ov;
    __nv_bfloat162* pq = (__nv_bfloat162*)&oq;
    __nv_bfloat162* pv = (__nv_bfloat162*)&ov;
    #pragma unroll
    for (int r = 0; r < 4; r++) {
        pq[r] = __nv_bfloat162(__float2bfloat16_rn(Aq[d*8 + 2*r]), __float2bfloat16_rn(Aq[d*8 + 2*r + 1]));
        pv[r] = __nv_bfloat162(__float2bfloat16_rn(Av[d*8 + 2*r]), __float2bfloat16_rn(Av[d*8 + 2*r + 1]));
    }
    g_Aq2[d] = oq;
    g_Av2[d] = ov;
}

// ---------------- fused: x+tp -> fp16 AND u = (x+tp)@A ----------------
__global__ void __launch_bounds__(256) k_prep(const float4* __restrict__ x4,
                                              const float4* __restrict__ tp4) {
    __shared__ uint4 sAq[1024];   // layout [c][d4]
    __shared__ uint4 sAv[1024];
    int tid = threadIdx.x;
    for (int i = tid; i < 1024; i += 256) {
        int p = (i & 3) * 256 + (i >> 2);
        sAq[p] = g_Aq2[i];
        sAv[p] = g_Av2[i];
    }
    __syncthreads();
    int w = tid >> 5, lane = tid & 31;
    int row = (blockIdx.x << 3) + w;
    int t = row & 3;
    const float4* xr = x4 + (size_t)row * 256;
    const float4* tr = tp4 + t * 256;
    __half2* Hx = (__half2*)(g_X + (size_t)row * 1024);
    float pq[8] = {0,0,0,0,0,0,0,0};
    float pv[8] = {0,0,0,0,0,0,0,0};
    #pragma unroll
    for (int j = 0; j < 8; j++) {
        int d4 = j*32 + lane;
        float4 v = xr[d4], p = tr[d4];
        v.x += p.x; v.y += p.y; v.z += p.z; v.w += p.w;
        Hx[2*d4]   = __halves2half2(__float2half_rn(v.x), __float2half_rn(v.y));
        Hx[2*d4+1] = __halves2half2(__float2half_rn(v.z), __float2half_rn(v.w));
        const float* ve = &v.x;
        #pragma unroll
        for (int c = 0; c < 4; c++) {
            float xe = ve[c];
            uint4 aq = sAq[c*256 + d4];
            uint4 av = sAv[c*256 + d4];
            const __nv_bfloat162* q2 = (const __nv_bfloat162*)&aq;
            const __nv_bfloat162* v2 = (const __nv_bfloat162*)&av;
            #pragma unroll
            for (int r = 0; r < 4; r++) {
                float2 fq = __bfloat1622float2(q2[r]);
                float2 fv = __bfloat1622float2(v2[r]);
                pq[2*r]   += xe * fq.x;
                pq[2*r+1] += xe * fq.y;
                pv[2*r]   += xe * fv.x;
                pv[2*r+1] += xe * fv.y;
            }
        }
    }
    #pragma unroll
    for (int off = 16; off > 0; off >>= 1)
        #pragma unroll
        for (int r = 0; r < 8; r++) {
            pq[r] += __shfl_xor_sync(0xffffffffu, pq[r], off);
            pv[r] += __shfl_xor_sync(0xffffffffu, pv[r], off);
        }
    if (lane == 0) {
        ((float4*)(g_uq + (size_t)row*8))[0] = make_float4(pq[0],pq[1],pq[2],pq[3]);
        ((float4*)(g_uq + (size_t)row*8))[1] = make_float4(pq[4],pq[5],pq[6],pq[7]);
        ((float4*)(g_uv + (size_t)row*8))[0] = make_float4(pv[0],pv[1],pv[2],pv[3]);
        ((float4*)(g_uv + (size_t)row*8))[1] = make_float4(pv[4],pv[5],pv[6],pv[7]);
    }
}

// ---------------- single-fp16 GEMM, CTA 128x128, warp 32x64, K-chunk 64, 3-stage ----------------
#define ASTAGE 18432              // 128 rows x 144B (64 cols + 8 pad)
#define BSTAGE 17408              // 64 rows x 272B (128 cols + 8 pad)
#define STAGE  (ASTAGE + BSTAGE)  // 35840
#define SMEM_BYTES (3*STAGE)      // 107520 -> 2 CTA/SM = 215040 <= 228KB
__device__ __forceinline__ uint32_t sA(int buf, int row, int col) {
    return (uint32_t)(buf*STAGE + row*144 + col*2);
}
__device__ __forceinline__ uint32_t sB(int buf, int row, int col) {
    return (uint32_t)(buf*STAGE + ASTAGE + row*272 + col*2);
}
#define CP16(dst, src) asm volatile("cp.async.cg.shared.global [%0], [%1], 16;\n" :: "r"(dst), "l"(src))
#define LDSM4(R, addr) asm volatile("ldmatrix.sync.aligned.m8n8.x4.shared.b16 {%0,%1,%2,%3}, [%4];\n" \
    : "=r"((R)[0]), "=r"((R)[1]), "=r"((R)[2]), "=r"((R)[3]) : "r"(addr))
#define LDSM4T(R, addr) asm volatile("ldmatrix.sync.aligned.m8n8.x4.trans.shared.b16 {%0,%1,%2,%3}, [%4];\n" \
    : "=r"((R)[0]), "=r"((R)[1]), "=r"((R)[2]), "=r"((R)[3]) : "r"(addr))
#define MMAF32(Dp, A, Bf) asm volatile( \
    "mma.sync.aligned.m16n8k16.row.col.f32.f16.f16.f32 {%0,%1,%2,%3},{%4,%5,%6,%7},{%8,%9},{%0,%1,%2,%3};\n" \
    : "+f"((Dp)[0]), "+f"((Dp)[1]), "+f"((Dp)[2]), "+f"((Dp)[3]) \
    : "r"((A)[0]), "r"((A)[1]), "r"((A)[2]), "r"((A)[3]), "r"((Bf)[0]), "r"((Bf)[1]))

__device__ __forceinline__ void store2(__half* p, float v0, float v1) {
    *(__half2*)p = __floats2half2_rn(v0, v1);
}
__device__ __forceinline__ void store2(float* p, float v0, float v1) {
    float2 o; o.x = v0; o.y = v1;
    *(float2*)p = o;
}

template<bool EPI, typename OT>
__global__ void __launch_bounds__(256, 2) k_gemm(
    const __half* __restrict__ Ag, const __half* __restrict__ Bg,
    OT* __restrict__ C, int N, int K,
    const float* __restrict__ bias, const float* __restrict__ P,
    const float* __restrict__ LB)
{
    extern __shared__ __align__(16) char smem[];
    uint32_t sb = (uint32_t)__cvta_generic_to_shared(smem);
    int tid = threadIdx.x;
    int bm = blockIdx.y << 7, bn = blockIdx.x << 7;
    int KT = K >> 6;

    float d[2][8][4];
    #pragma unroll
    for (int i = 0; i < 2; i++)
        #pragma unroll
        for (int j = 0; j < 8; j++) { d[i][j][0]=0.f; d[i][j][1]=0.f; d[i][j][2]=0.f; d[i][j][3]=0.f; }

    int w = tid >> 5, lane = tid & 31;
    int wm = w & 3, wn = w >> 2;
    int ar0 = tid >> 3, akc = (tid & 7) << 3;    // A: 8 chunks/row (128B), rows via +32 steps
    int br0 = tid >> 4, bnc = (tid & 15) << 3;   // B: 16 chunks/row (256B)

    auto load_stage = [&](int kt, int buf) {
        #pragma unroll
        for (int i = 0; i < 4; i++) {
            int arow = ar0 + i*32;
            CP16(sb + sA(buf, arow, akc), Ag + (size_t)(bm + arow) * K + (kt<<6) + akc);
        }
        #pragma unroll
        for (int i = 0; i < 4; i++) {
            int brow = br0 + i*16;
            CP16(sb + sB(buf, brow, bnc), Bg + (size_t)((kt<<6) + brow) * N + bn + bnc);
        }
        asm volatile("cp.async.commit_group;\n");
    };

    load_stage(0, 0);
    load_stage(1, 1);
    int sub = lane >> 3, rr = lane & 7;
    int bl15 = lane & 15, blh = (lane >> 4) << 3;

    for (int kt = 0; kt < KT; kt++) {
        if (kt + 1 < KT) asm volatile("cp.async.wait_group 1;\n" ::: "memory");
        else             asm volatile("cp.async.wait_group 0;\n" ::: "memory");
        __syncthreads();
        int buf = kt % 3;
        if (kt + 2 < KT) load_stage(kt + 2, (kt + 2) % 3);
        #pragma unroll
        for (int ks = 0; ks < 4; ks++) {
            uint32_t a[2][4];
            #pragma unroll
            for (int mt = 0; mt < 2; mt++) {
                int arow = (wm<<5) + (mt<<4) + ((sub&1)<<3) + rr;
                int acol = (ks<<4) + ((sub>>1)<<3);
                LDSM4(a[mt], sb + sA(buf, arow, acol));
            }
            uint32_t b[8][2];
            int krow = (ks<<4) + bl15;
            #pragma unroll
            for (int p = 0; p < 4; p++) {
                uint32_t r4[4];
                int bcol = (wn<<6) + (p<<4) + blh;
                LDSM4T(r4, sb + sB(buf, krow, bcol));
                b[2*p][0] = r4[0];   b[2*p][1] = r4[1];
                b[2*p+1][0] = r4[2]; b[2*p+1][1] = r4[3];
            }
            #pragma unroll
            for (int mt = 0; mt < 2; mt++)
                #pragma unroll
                for (int nt = 0; nt < 8; nt++)
                    MMAF32(d[mt][nt], a[mt], b[nt]);
        }
    }

    int g = lane >> 2, tq = (lane & 3) << 1;
    #pragma unroll
    for (int mt = 0; mt < 2; mt++)
        #pragma unroll
        for (int e2 = 0; e2 < 2; e2++) {
            int row = bm + (wm<<5) + (mt<<4) + (e2<<3) + g;
            float p0=0,p1=0,p2=0,p3=0,p4=0,p5=0,p6=0,p7=0;
            if (EPI) {
                const float* pr = P + (size_t)row*8;
                p0=pr[0];p1=pr[1];p2=pr[2];p3=pr[3];
                p4=pr[4];p5=pr[5];p6=pr[6];p7=pr[7];
            }
            #pragma unroll
            for (int nt = 0; nt < 8; nt++) {
                int col = bn + (wn<<6) + (nt<<3) + tq;
                float v0 = d[mt][nt][e2*2], v1 = d[mt][nt][e2*2+1];
                if (EPI) {
                    v0 += bias[col] + 2.f*(p0*LB[col] + p1*LB[N+col] + p2*LB[2*N+col] + p3*LB[3*N+col]
                        + p4*LB[4*N+col] + p5*LB[5*N+col] + p6*LB[6*N+col] + p7*LB[7*N+col]);
                    v1 += bias[col+1] + 2.f*(p0*LB[col+1] + p1*LB[N+col+1] + p2*LB[2*N+col+1] + p3*LB[3*N+col+1]
                        + p4*LB[4*N+col+1] + p5*LB[5*N+col+1] + p6*LB[6*N+col+1] + p7*LB[7*N+col+1]);
                }
                store2(C + (size_t)row*N + col, v0, v1);
            }
        }
}

// ---------------- attention + mean + M + P ----------------
__global__ void __launch_bounds__(512) k_attn(const float* __restrict__ Bq,
                                              const float* __restrict__ Bv,
                                              const float* __restrict__ Apj) {
    __shared__ float pacc[8];
    int tid = threadIdx.x;
    if (tid < 8) pacc[tid] = 0.f;
    __syncthreads();
    int b = blockIdx.x;
    int h = tid >> 5, lane = tid & 31;
    int row0 = b << 2;
    int c0 = (h << 6) + lane;

    float q[4][2], k[4][2], v[4][2];
    #pragma unroll
    for (int t = 0; t < 4; t++) {
        size_t base = (size_t)(row0 + t) * 3072;
        const float* uqr = g_uq + (size_t)(row0 + t) * 8;
        const float* uvr = g_uv + (size_t)(row0 + t) * 8;
        float dq0=0, dq1=0, dv0=0, dv1=0;
        #pragma unroll
        for (int r = 0; r < 8; r++) {
            float uqv = uqr[r], uvv = uvr[r];
            dq0 += uqv * Bq[r*1024 + c0];
            dq1 += uqv * Bq[r*1024 + c0 + 32];
            dv0 += uvv * Bv[r*1024 + c0];
            dv1 += uvv * Bv[r*1024 + c0 + 32];
        }
        q[t][0] = __half2float(g_qkv[base + c0])        + 2.f*dq0;
        q[t][1] = __half2float(g_qkv[base + c0 + 32])   + 2.f*dq1;
        k[t][0] = __half2float(g_qkv[base + 1024 + c0]);
        k[t][1] = __half2float(g_qkv[base + 1024 + c0 + 32]);
        v[t][0] = __half2float(g_qkv[base + 2048 + c0])      + 2.f*dv0;
        v[t][1] = __half2float(g_qkv[base + 2048 + c0 + 32]) + 2.f*dv1;
    }
    float sc[4][4];
    #pragma unroll
    for (int t = 0; t < 4; t++)
        #pragma unroll
        for (int s = 0; s < 4; s++) {
            float p = q[t][0]*k[s][0] + q[t][1]*k[s][1];
            #pragma unroll
            for (int off = 16; off > 0; off >>= 1)
                p += __shfl_xor_sync(0xffffffffu, p, off);
            sc[t][s] = p * 0.125f;
        }
    float a0 = 0.f, a1 = 0.f;
    #pragma unroll
    for (int t = 0; t < 4; t++) {
        float m = fmaxf(fmaxf(sc[t][0], sc[t][1]), fmaxf(sc[t][2], sc[t][3]));
        float e0 = __expf(sc[t][0]-m), e1 = __expf(sc[t][1]-m);
        float e2 = __expf(sc[t][2]-m), e3 = __expf(sc[t][3]-m);
        float inv = 1.f / (e0+e1+e2+e3);
        a0 += (e0*v[0][0] + e1*v[1][0] + e2*v[2][0] + e3*v[3][0]) * inv;
        a1 += (e0*v[0][1] + e1*v[1][1] + e2*v[2][1] + e3*v[3][1]) * inv;
    }
    a0 *= 0.25f; a1 *= 0.25f;
    size_t oi = (size_t)b*1024 + c0;
    g_M[oi]    = __float2half_rn(a0);
    g_M[oi+32] = __float2half_rn(a1);
    float pp[8];
    #pragma unroll
    for (int r = 0; r < 8; r++)
        pp[r] = a0 * Apj[(size_t)c0*8 + r] + a1 * Apj[(size_t)(c0+32)*8 + r];
    #pragma unroll
    for (int off = 16; off > 0; off >>= 1)
        #pragma unroll
        for (int r = 0; r < 8; r++)
            pp[r] += __shfl_xor_sync(0xffffffffu, pp[r], off);
    if (lane == 0) {
        #pragma unroll
        for (int r = 0; r < 8; r++) atomicAdd(&pacc[r], pp[r]);
    }
    __syncthreads();
    if (tid < 8) g_P[(size_t)b*8 + tid] = pacc[tid];
}

extern "C" void kernel_launch(void* const* d_in, const int* in_sizes, int n_in,
                              void* d_out, int out_size) {
    const float* x    = (const float*)d_in[0];
    const float* tp   = (const float*)d_in[1];
    const float* Wqkv = (const float*)d_in[2];
    const float* lqA  = (const float*)d_in[3];
    const float* lqB  = (const float*)d_in[4];
    const float* lvA  = (const float*)d_in[5];
    const float* lvB  = (const float*)d_in[6];
    const float* Wp   = (const float*)d_in[7];
    const float* bp   = (const float*)d_in[8];
    const float* lpA  = (const float*)d_in[9];
    const float* lpB  = (const float*)d_in[10];
    float* out = (float*)d_out;

    static bool attr_set = false;
    if (!attr_set) {
        cudaFuncSetAttribute(k_gemm<false, __half>, cudaFuncAttributeMaxDynamicSharedMemorySize, SMEM_BYTES);
        cudaFuncSetAttribute(k_gemm<true, float>,   cudaFuncAttributeMaxDynamicSharedMemorySize, SMEM_BYTES);
        attr_set = true;
    }

    void *pX, *pW1, *pW2, *pQkv, *pM, *pP;
    cudaGetSymbolAddress(&pX,  g_X);
    cudaGetSymbolAddress(&pW1, g_W1);
    cudaGetSymbolAddress(&pW2, g_W2);
    cudaGetSymbolAddress(&pQkv, g_qkv);
    cudaGetSymbolAddress(&pM,  g_M);
    cudaGetSymbolAddress(&pP,  g_P);

    k_convert<<<3072, 256>>>(Wqkv, (__half*)pW1, 786432);
    k_convert<<<1024, 256>>>(Wp,   (__half*)pW2, 262144);
    k_convA<<<4, 256>>>(lqA, lvA);
    k_prep<<<8192, 256>>>((const float4*)x, (const float4*)tp);

    k_gemm<false, __half><<<dim3(24, 512), 256, SMEM_BYTES>>>(
        (const __half*)pX, (const __half*)pW1,
        (__half*)pQkv, N1, D_, nullptr, nullptr, nullptr);

    k_attn<<<B_, 512>>>(lqB, lvB, lpA);

    k_gemm<true, float><<<dim3(8, 128), 256, SMEM_BYTES>>>(
        (const __half*)pM, (const __half*)pW2,
        out, D_, D_, bp, (const float*)pP, lpB);
}

// round 15
// speedup vs baseline: 1.2365x; 1.0670x over previous
#include <cuda_runtime.h>
#include <cuda_fp16.h>
#include <cuda_bf16.h>
#include <cstdint>

#define B_   16384
#define T_   4
#define D_   1024
#define MROWS (B_*T_)
#define N1   (3*D_)

__device__ __half g_X [(size_t)MROWS*D_];
__device__ __half g_W1[(size_t)D_*N1];
__device__ __half g_W2[(size_t)D_*D_];
__device__ __half g_qkv[(size_t)MROWS*N1];
__device__ float  g_uq[(size_t)MROWS*8];
__device__ float  g_uv[(size_t)MROWS*8];
__device__ __half g_M [(size_t)B_*D_];
__device__ float  g_P [(size_t)B_*8];
__device__ uint4  g_Aq2[1024];
__device__ uint4  g_Av2[1024];

// ---------------- fp32 -> fp16 convert ----------------
__global__ void k_convert(const float* __restrict__ src, __half* __restrict__ dst, int n4) {
    int i = blockIdx.x * blockDim.x + threadIdx.x;
    if (i >= n4) return;
    float4 v = ((const float4*)src)[i];
    ((__half2*)dst)[2*i]   = __halves2half2(__float2half_rn(v.x), __float2half_rn(v.y));
    ((__half2*)dst)[2*i+1] = __halves2half2(__float2half_rn(v.z), __float2half_rn(v.w));
}

// ---------------- LoRA-A -> packed bf16 ----------------
__global__ void k_convA(const float* __restrict__ Aq, const float* __restrict__ Av) {
    int d = blockIdx.x * 256 + threadIdx.x;
    if (d >= 1024) return;
    uint4 oq, ov;
    __nv_bfloat162* pq = (__nv_bfloat162*)&oq;
    __nv_bfloat162* pv = (__nv_bfloat162*)&ov;
    #pragma unroll
    for (int r = 0; r < 4; r++) {
        pq[r] = __nv_bfloat162(__float2bfloat16_rn(Aq[d*8 + 2*r]), __float2bfloat16_rn(Aq[d*8 + 2*r + 1]));
        pv[r] = __nv_bfloat162(__float2bfloat16_rn(Av[d*8 + 2*r]), __float2bfloat16_rn(Av[d*8 + 2*r + 1]));
    }
    g_Aq2[d] = oq;
    g_Av2[d] = ov;
}

// ---------------- fused: x+tp -> fp16 AND u = (x+tp)@A ----------------
__global__ void __launch_bounds__(256) k_prep(const float4* __restrict__ x4,
                                              const float4* __restrict__ tp4) {
    __shared__ uint4 sAq[1024];   // layout [c][d4]
    __shared__ uint4 sAv[1024];
    int tid = threadIdx.x;
    for (int i = tid; i < 1024; i += 256) {
        int p = (i & 3) * 256 + (i >> 2);
        sAq[p] = g_Aq2[i];
        sAv[p] = g_Av2[i];
    }
    __syncthreads();
    int w = tid >> 5, lane = tid & 31;
    int row = (blockIdx.x << 3) + w;
    int t = row & 3;
    const float4* xr = x4 + (size_t)row * 256;
    const float4* tr = tp4 + t * 256;
    __half2* Hx = (__half2*)(g_X + (size_t)row * 1024);
    float pq[8] = {0,0,0,0,0,0,0,0};
    float pv[8] = {0,0,0,0,0,0,0,0};
    #pragma unroll
    for (int j = 0; j < 8; j++) {
        int d4 = j*32 + lane;
        float4 v = xr[d4], p = tr[d4];
        v.x += p.x; v.y += p.y; v.z += p.z; v.w += p.w;
        Hx[2*d4]   = __halves2half2(__float2half_rn(v.x), __float2half_rn(v.y));
        Hx[2*d4+1] = __halves2half2(__float2half_rn(v.z), __float2half_rn(v.w));
        const float* ve = &v.x;
        #pragma unroll
        for (int c = 0; c < 4; c++) {
            float xe = ve[c];
            uint4 aq = sAq[c*256 + d4];
            uint4 av = sAv[c*256 + d4];
            const __nv_bfloat162* q2 = (const __nv_bfloat162*)&aq;
            const __nv_bfloat162* v2 = (const __nv_bfloat162*)&av;
            #pragma unroll
            for (int r = 0; r < 4; r++) {
                float2 fq = __bfloat1622float2(q2[r]);
                float2 fv = __bfloat1622float2(v2[r]);
                pq[2*r]   += xe * fq.x;
                pq[2*r+1] += xe * fq.y;
                pv[2*r]   += xe * fv.x;
                pv[2*r+1] += xe * fv.y;
            }
        }
    }
    #pragma unroll
    for (int off = 16; off > 0; off >>= 1)
        #pragma unroll
        for (int r = 0; r < 8; r++) {
            pq[r] += __shfl_xor_sync(0xffffffffu, pq[r], off);
            pv[r] += __shfl_xor_sync(0xffffffffu, pv[r], off);
        }
    if (lane == 0) {
        ((float4*)(g_uq + (size_t)row*8))[0] = make_float4(pq[0],pq[1],pq[2],pq[3]);
        ((float4*)(g_uq + (size_t)row*8))[1] = make_float4(pq[4],pq[5],pq[6],pq[7]);
        ((float4*)(g_uv + (size_t)row*8))[0] = make_float4(pv[0],pv[1],pv[2],pv[3]);
        ((float4*)(g_uv + (size_t)row*8))[1] = make_float4(pv[4],pv[5],pv[6],pv[7]);
    }
}

// ---------------- single-fp16 GEMM, CTA 128x128, warp 32x64, K-chunk 64, 2-stage ----------------
#define ASTAGE 18432              // 128 rows x 144B (64 cols + 8 pad)
#define BSTAGE 17408              // 64 rows x 272B (128 cols + 8 pad)
#define STAGE  (ASTAGE + BSTAGE)  // 35840
#define SMEM_BYTES (2*STAGE)      // 71680
__device__ __forceinline__ uint32_t sA(int buf, int row, int col) {
    return (uint32_t)(buf*STAGE + row*144 + col*2);
}
__device__ __forceinline__ uint32_t sB(int buf, int row, int col) {
    return (uint32_t)(buf*STAGE + ASTAGE + row*272 + col*2);
}
#define CP16(dst, src) asm volatile("cp.async.cg.shared.global [%0], [%1], 16;\n" :: "r"(dst), "l"(src))
#define LDSM4(R, addr) asm volatile("ldmatrix.sync.aligned.m8n8.x4.shared.b16 {%0,%1,%2,%3}, [%4];\n" \
    : "=r"((R)[0]), "=r"((R)[1]), "=r"((R)[2]), "=r"((R)[3]) : "r"(addr))
#define LDSM4T(R, addr) asm volatile("ldmatrix.sync.aligned.m8n8.x4.trans.shared.b16 {%0,%1,%2,%3}, [%4];\n" \
    : "=r"((R)[0]), "=r"((R)[1]), "=r"((R)[2]), "=r"((R)[3]) : "r"(addr))
#define MMAF32(Dp, A, Bf) asm volatile( \
    "mma.sync.aligned.m16n8k16.row.col.f32.f16.f16.f32 {%0,%1,%2,%3},{%4,%5,%6,%7},{%8,%9},{%0,%1,%2,%3};\n" \
    : "+f"((Dp)[0]), "+f"((Dp)[1]), "+f"((Dp)[2]), "+f"((Dp)[3]) \
    : "r"((A)[0]), "r"((A)[1]), "r"((A)[2]), "r"((A)[3]), "r"((Bf)[0]), "r"((Bf)[1]))

__device__ __forceinline__ void store2(__half* p, float v0, float v1) {
    *(__half2*)p = __floats2half2_rn(v0, v1);
}
__device__ __forceinline__ void store2(float* p, float v0, float v1) {
    float2 o; o.x = v0; o.y = v1;
    *(float2*)p = o;
}

template<bool EPI, typename OT>
__global__ void __launch_bounds__(256, 2) k_gemm(
    const __half* __restrict__ Ag, const __half* __restrict__ Bg,
    OT* __restrict__ C, int N, int K,
    const float* __restrict__ bias, const float* __restrict__ P,
    const float* __restrict__ LB)
{
    extern __shared__ __align__(16) char smem[];
    uint32_t sb = (uint32_t)__cvta_generic_to_shared(smem);
    int tid = threadIdx.x;
    int bm = blockIdx.y << 7, bn = blockIdx.x << 7;
    int KT = K >> 6;

    float d[2][8][4];
    #pragma unroll
    for (int i = 0; i < 2; i++)
        #pragma unroll
        for (int j = 0; j < 8; j++) { d[i][j][0]=0.f; d[i][j][1]=0.f; d[i][j][2]=0.f; d[i][j][3]=0.f; }

    int w = tid >> 5, lane = tid & 31;
    int wm = w & 3, wn = w >> 2;
    int ar0 = tid >> 3, akc = (tid & 7) << 3;    // A: 8 chunks/row (128B), rows via +32 steps
    int br0 = tid >> 4, bnc = (tid & 15) << 3;   // B: 16 chunks/row (256B)

    auto load_stage = [&](int kt, int buf) {
        #pragma unroll
        for (int i = 0; i < 4; i++) {
            int arow = ar0 + i*32;
            CP16(sb + sA(buf, arow, akc), Ag + (size_t)(bm + arow) * K + (kt<<6) + akc);
        }
        #pragma unroll
        for (int i = 0; i < 4; i++) {
            int brow = br0 + i*16;
            CP16(sb + sB(buf, brow, bnc), Bg + (size_t)((kt<<6) + brow) * N + bn + bnc);
        }
        asm volatile("cp.async.commit_group;\n");
    };

    load_stage(0, 0);
    int sub = lane >> 3, rr = lane & 7;
    int bl15 = lane & 15, blh = (lane >> 4) << 3;

    for (int kt = 0; kt < KT; kt++) {
        asm volatile("cp.async.wait_group 0;\n" ::: "memory");
        __syncthreads();
        int buf = kt & 1;
        if (kt + 1 < KT) load_stage(kt + 1, buf ^ 1);
        #pragma unroll
        for (int ks = 0; ks < 4; ks++) {
            uint32_t a[2][4];
            #pragma unroll
            for (int mt = 0; mt < 2; mt++) {
                int arow = (wm<<5) + (mt<<4) + ((sub&1)<<3) + rr;
                int acol = (ks<<4) + ((sub>>1)<<3);
                LDSM4(a[mt], sb + sA(buf, arow, acol));
            }
            uint32_t b[8][2];
            int krow = (ks<<4) + bl15;
            #pragma unroll
            for (int p = 0; p < 4; p++) {
                uint32_t r4[4];
                int bcol = (wn<<6) + (p<<4) + blh;
                LDSM4T(r4, sb + sB(buf, krow, bcol));
                b[2*p][0] = r4[0];   b[2*p][1] = r4[1];
                b[2*p+1][0] = r4[2]; b[2*p+1][1] = r4[3];
            }
            #pragma unroll
            for (int mt = 0; mt < 2; mt++)
                #pragma unroll
                for (int nt = 0; nt < 8; nt++)
                    MMAF32(d[mt][nt], a[mt], b[nt]);
        }
    }

    int g = lane >> 2, tq = (lane & 3) << 1;
    #pragma unroll
    for (int mt = 0; mt < 2; mt++)
        #pragma unroll
        for (int e2 = 0; e2 < 2; e2++) {
            int row = bm + (wm<<5) + (mt<<4) + (e2<<3) + g;
            float p0=0,p1=0,p2=0,p3=0,p4=0,p5=0,p6=0,p7=0;
            if (EPI) {
                const float* pr = P + (size_t)row*8;
                p0=pr[0];p1=pr[1];p2=pr[2];p3=pr[3];
                p4=pr[4];p5=pr[5];p6=pr[6];p7=pr[7];
            }
            #pragma unroll
            for (int nt = 0; nt < 8; nt++) {
                int col = bn + (wn<<6) + (nt<<3) + tq;
                float v0 = d[mt][nt][e2*2], v1 = d[mt][nt][e2*2+1];
                if (EPI) {
                    v0 += bias[col] + 2.f*(p0*LB[col] + p1*LB[N+col] + p2*LB[2*N+col] + p3*LB[3*N+col]
                        + p4*LB[4*N+col] + p5*LB[5*N+col] + p6*LB[6*N+col] + p7*LB[7*N+col]);
                    v1 += bias[col+1] + 2.f*(p0*LB[col+1] + p1*LB[N+col+1] + p2*LB[2*N+col+1] + p3*LB[3*N+col+1]
                        + p4*LB[4*N+col+1] + p5*LB[5*N+col+1] + p6*LB[6*N+col+1] + p7*LB[7*N+col+1]);
                }
                store2(C + (size_t)row*N + col, v0, v1);
            }
        }
}

// ---------------- attention + mean + M + P (vectorized, hoisted B) ----------------
__global__ void __launch_bounds__(512) k_attn(const float* __restrict__ Bq,
                                              const float* __restrict__ Bv,
                                              const float* __restrict__ Apj) {
    __shared__ float pacc[8];
    int tid = threadIdx.x;
    if (tid < 8) pacc[tid] = 0.f;
    __syncthreads();
    int b = blockIdx.x;
    int h = tid >> 5, lane = tid & 31;
    int row0 = b << 2;
    int c0 = (h << 6) + (lane << 1);          // two consecutive columns per thread

    // hoisted LoRA-B loads (loop-invariant over t)
    float2 Bq2[8], Bv2[8];
    #pragma unroll
    for (int r = 0; r < 8; r++) {
        Bq2[r] = *(const float2*)(Bq + r*1024 + c0);
        Bv2[r] = *(const float2*)(Bv + r*1024 + c0);
    }

    float q[4][2], k[4][2], v[4][2];
    #pragma unroll
    for (int t = 0; t < 4; t++) {
        size_t base = (size_t)(row0 + t) * 3072;
        const float4* ur = (const float4*)(g_uq + (size_t)(row0 + t) * 8);
        const float4* vr = (const float4*)(g_uv + (size_t)(row0 + t) * 8);
        float4 u0 = ur[0], u1 = ur[1];
        float4 w0 = vr[0], w1 = vr[1];
        float uq[8] = {u0.x,u0.y,u0.z,u0.w,u1.x,u1.y,u1.z,u1.w};
        float uv[8] = {w0.x,w0.y,w0.z,w0.w,w1.x,w1.y,w1.z,w1.w};
        float dq0=0, dq1=0, dv0=0, dv1=0;
        #pragma unroll
        for (int r = 0; r < 8; r++) {
            dq0 += uq[r] * Bq2[r].x;
            dq1 += uq[r] * Bq2[r].y;
            dv0 += uv[r] * Bv2[r].x;
            dv1 += uv[r] * Bv2[r].y;
        }
        float2 fq = __half22float2(*(const __half2*)(g_qkv + base + c0));
        float2 fk = __half22float2(*(const __half2*)(g_qkv + base + 1024 + c0));
        float2 fv = __half22float2(*(const __half2*)(g_qkv + base + 2048 + c0));
        q[t][0] = fq.x + 2.f*dq0;  q[t][1] = fq.y + 2.f*dq1;
        k[t][0] = fk.x;            k[t][1] = fk.y;
        v[t][0] = fv.x + 2.f*dv0;  v[t][1] = fv.y + 2.f*dv1;
    }
    float sc[4][4];
    #pragma unroll
    for (int t = 0; t < 4; t++)
        #pragma unroll
        for (int s = 0; s < 4; s++) {
            float p = q[t][0]*k[s][0] + q[t][1]*k[s][1];
            #pragma unroll
            for (int off = 16; off > 0; off >>= 1)
                p += __shfl_xor_sync(0xffffffffu, p, off);
            sc[t][s] = p * 0.125f;
        }
    float a0 = 0.f, a1 = 0.f;
    #pragma unroll
    for (int t = 0; t < 4; t++) {
        float m = fmaxf(fmaxf(sc[t][0], sc[t][1]), fmaxf(sc[t][2], sc[t][3]));
        float e0 = __expf(sc[t][0]-m), e1 = __expf(sc[t][1]-m);
        float e2 = __expf(sc[t][2]-m), e3 = __expf(sc[t][3]-m);
        float inv = 1.f / (e0+e1+e2+e3);
        a0 += (e0*v[0][0] + e1*v[1][0] + e2*v[2][0] + e3*v[3][0]) * inv;
        a1 += (e0*v[0][1] + e1*v[1][1] + e2*v[2][1] + e3*v[3][1]) * inv;
    }
    a0 *= 0.25f; a1 *= 0.25f;
    size_t oi = (size_t)b*1024 + c0;
    *(__half2*)(g_M + oi) = __floats2half2_rn(a0, a1);
    // P[b][r] += a0*Apj[c0][r] + a1*Apj[c0+1][r]
    const float4* ap0 = (const float4*)(Apj + (size_t)c0*8);
    float4 A0 = ap0[0], A1 = ap0[1], A2 = ap0[2], A3 = ap0[3];
    float pp[8] = {
        a0*A0.x + a1*A2.x, a0*A0.y + a1*A2.y, a0*A0.z + a1*A2.z, a0*A0.w + a1*A2.w,
        a0*A1.x + a1*A3.x, a0*A1.y + a1*A3.y, a0*A1.z + a1*A3.z, a0*A1.w + a1*A3.w };
    #pragma unroll
    for (int off = 16; off > 0; off >>= 1)
        #pragma unroll
        for (int r = 0; r < 8; r++)
            pp[r] += __shfl_xor_sync(0xffffffffu, pp[r], off);
    if (lane == 0) {
        #pragma unroll
        for (int r = 0; r < 8; r++) atomicAdd(&pacc[r], pp[r]);
    }
    __syncthreads();
    if (tid < 8) g_P[(size_t)b*8 + tid] = pacc[tid];
}

extern "C" void kernel_launch(void* const* d_in, const int* in_sizes, int n_in,
                              void* d_out, int out_size) {
    const float* x    = (const float*)d_in[0];
    const float* tp   = (const float*)d_in[1];
    const float* Wqkv = (const float*)d_in[2];
    const float* lqA  = (const float*)d_in[3];
    const float* lqB  = (const float*)d_in[4];
    const float* lvA  = (const float*)d_in[5];
    const float* lvB  = (const float*)d_in[6];
    const float* Wp   = (const float*)d_in[7];
    const float* bp   = (const float*)d_in[8];
    const float* lpA  = (const float*)d_in[9];
    const float* lpB  = (const float*)d_in[10];
    float* out = (float*)d_out;

    static bool attr_set = false;
    if (!attr_set) {
        cudaFuncSetAttribute(k_gemm<false, __half>, cudaFuncAttributeMaxDynamicSharedMemorySize, SMEM_BYTES);
        cudaFuncSetAttribute(k_gemm<true, float>,   cudaFuncAttributeMaxDynamicSharedMemorySize, SMEM_BYTES);
        attr_set = true;
    }

    void *pX, *pW1, *pW2, *pQkv, *pM, *pP;
    cudaGetSymbolAddress(&pX,  g_X);
    cudaGetSymbolAddress(&pW1, g_W1);
    cudaGetSymbolAddress(&pW2, g_W2);
    cudaGetSymbolAddress(&pQkv, g_qkv);
    cudaGetSymbolAddress(&pM,  g_M);
    cudaGetSymbolAddress(&pP,  g_P);

    k_convert<<<3072, 256>>>(Wqkv, (__half*)pW1, 786432);
    k_convert<<<1024, 256>>>(Wp,   (__half*)pW2, 262144);
    k_convA<<<4, 256>>>(lqA, lvA);
    k_prep<<<8192, 256>>>((const float4*)x, (const float4*)tp);

    k_gemm<false, __half><<<dim3(24, 512), 256, SMEM_BYTES>>>(
        (const __half*)pX, (const __half*)pW1,
        (__half*)pQkv, N1, D_, nullptr, nullptr, nullptr);

    k_attn<<<B_, 512>>>(lqB, lvB, lpA);

    k_gemm<true, float><<<dim3(8, 128), 256, SMEM_BYTES>>>(
        (const __half*)pM, (const __half*)pW2,
        out, D_, D_, bp, (const float*)pP, lpB);
}